// round 16
// baseline (speedup 1.0000x reference)
#include <cuda_runtime.h>
#include <cuda_bf16.h>
#include <cuda_fp16.h>
#include <math.h>
#include <cstdint>

// ---------------- problem constants ----------------
#define BATCH 8
#define SEQ 2048
#define TOK (BATCH*SEQ)          // 16384
#define DMODEL 512
#define DINNER 1024
#define DSTATE 128
#define NHEADS 16
#define HEADDIM 64
#define CONVDIM 1280
#define DINPROJ 2320
#define FF 2048
#define CHUNK 128
#define NCHUNK (SEQ/CHUNK)       // 16
#define NBLK (BATCH*NCHUNK*NHEADS) // 2048
#define NGC (BATCH*NCHUNK)       // 128
#define EPSF 1e-5f

#define MMA_F16(cc, aa, b0, b1) \
    asm volatile("mma.sync.aligned.m16n8k16.row.col.f32.f16.f16.f32 " \
        "{%0,%1,%2,%3},{%4,%5,%6,%7},{%8,%9},{%0,%1,%2,%3};" \
        : "+f"(cc[0]), "+f"(cc[1]), "+f"(cc[2]), "+f"(cc[3]) \
        : "r"(aa[0]), "r"(aa[1]), "r"(aa[2]), "r"(aa[3]), "r"(b0), "r"(b1))

#define MMA_BF16(cc, aa, b0, b1) \
    asm volatile("mma.sync.aligned.m16n8k16.row.col.f32.bf16.bf16.f32 " \
        "{%0,%1,%2,%3},{%4,%5,%6,%7},{%8,%9},{%0,%1,%2,%3};" \
        : "+f"(cc[0]), "+f"(cc[1]), "+f"(cc[2]), "+f"(cc[3]) \
        : "r"(aa[0]), "r"(aa[1]), "r"(aa[2]), "r"(aa[3]), "r"(b0), "r"(b1))

#define LDSM_X4(r, addr) \
    asm volatile("ldmatrix.sync.aligned.m8n8.x4.shared.b16 {%0,%1,%2,%3},[%4];" \
        : "=r"((r)[0]), "=r"((r)[1]), "=r"((r)[2]), "=r"((r)[3]) : "r"(addr))

#define LDSM_X4T(r, addr) \
    asm volatile("ldmatrix.sync.aligned.m8n8.x4.trans.shared.b16 {%0,%1,%2,%3},[%4];" \
        : "=r"((r)[0]), "=r"((r)[1]), "=r"((r)[2]), "=r"((r)[3]) : "r"(addr))

#define CP_ASYNC16(dst, src) \
    asm volatile("cp.async.cg.shared.global [%0], [%1], 16;" :: "r"(dst), "l"(src))
#define CP_COMMIT() asm volatile("cp.async.commit_group;" ::: "memory")
#define CP_WAIT2()  asm volatile("cp.async.wait_group 2;" ::: "memory")
#define CP_WAIT0()  asm volatile("cp.async.wait_group 0;" ::: "memory")

// ---------------- scratch ----------------
__device__ __align__(16) float g_zx[TOK*DINPROJ];
__device__ __align__(16) float g_xbc[TOK*CONVDIM];
__device__ __align__(16) float g_dt[NBLK*CHUNK];
__device__ __align__(16) float g_acs[NBLK*CHUNK];
__device__ __align__(16) float g_states[(size_t)NBLK*DSTATE*HEADDIM];
__device__ __align__(16) float g_prev[(size_t)NBLK*DSTATE*HEADDIM];
__device__ __align__(16) float g_y[(size_t)TOK*DINNER];
__device__ __align__(16) float g_mo[(size_t)TOK*DMODEL];
__device__ __align__(16) float g_t[(size_t)TOK*DMODEL];
__device__ __align__(16) float g_f2[(size_t)TOK*DMODEL];
__device__ __align__(16) float g_G[(size_t)NGC*CHUNK*CHUNK];
// fp16 operands: A side [hi|lo] pitch 2K, W side [hi] pitch K
__device__ __align__(16) __half g_A2[(size_t)TOK*2*DINNER];
__device__ __align__(16) __half g_A2b[(size_t)TOK*2*FF];
__device__ __align__(16) __half g_W2[DINPROJ*DMODEL];

// ---------------- helpers ----------------
__device__ __forceinline__ void blockReduce2(float& a, float& b, float* sh) {
    int lane = threadIdx.x & 31, w = threadIdx.x >> 5;
    #pragma unroll
    for (int o = 16; o; o >>= 1) {
        a += __shfl_xor_sync(0xffffffffu, a, o);
        b += __shfl_xor_sync(0xffffffffu, b, o);
    }
    if (lane == 0) { sh[w] = a; sh[32 + w] = b; }
    __syncthreads();
    int nw = blockDim.x >> 5;
    if (w == 0) {
        a = (lane < nw) ? sh[lane] : 0.f;
        b = (lane < nw) ? sh[32 + lane] : 0.f;
        #pragma unroll
        for (int o = 16; o; o >>= 1) {
            a += __shfl_xor_sync(0xffffffffu, a, o);
            b += __shfl_xor_sync(0xffffffffu, b, o);
        }
        if (lane == 0) { sh[0] = a; sh[32] = b; }
    }
    __syncthreads();
    a = sh[0]; b = sh[32];
}

__device__ __forceinline__ void f16x2_store_scalar(__half* row, int K, int d, float s) {
    __half hi = __float2half_rn(s);
    __half lo = __float2half_rn(s - __half2float(hi));
    row[d] = hi; row[K + d] = lo;
}

__device__ __forceinline__ void split4(float4 v, __half* hi, __half* lo, int o) {
    __half2 h0, h1, l0, l1;
    h0.x = __float2half_rn(v.x); h0.y = __float2half_rn(v.y);
    h1.x = __float2half_rn(v.z); h1.y = __float2half_rn(v.w);
    l0.x = __float2half_rn(v.x - __half2float(h0.x));
    l0.y = __float2half_rn(v.y - __half2float(h0.y));
    l1.x = __float2half_rn(v.z - __half2float(h1.x));
    l1.y = __float2half_rn(v.w - __half2float(h1.y));
    *(__half2*)&hi[o] = h0; *(__half2*)&hi[o + 2] = h1;
    *(__half2*)&lo[o] = l0; *(__half2*)&lo[o + 2] = l1;
}

__device__ __forceinline__ void hi4(float4 v, __half* hi, int o) {
    __half2 h0, h1;
    h0.x = __float2half_rn(v.x); h0.y = __float2half_rn(v.y);
    h1.x = __float2half_rn(v.z); h1.y = __float2half_rn(v.w);
    *(__half2*)&hi[o] = h0; *(__half2*)&hi[o + 2] = h1;
}

// ---------------- A-split: src[M,K] fp32 -> dst[M,2K] f16 (hi | lo) ----------------
__global__ void k_splitA(const float* __restrict__ src, __half* __restrict__ dst, int K) {
    size_t i = (size_t)blockIdx.x * 256 + threadIdx.x;
    int K4 = K >> 2;
    size_t row = i / K4;
    int c4 = (int)(i % K4);
    float4 v = ((const float4*)src)[i];
    __half2 h0, h1, l0, l1;
    h0.x = __float2half_rn(v.x); h0.y = __float2half_rn(v.y);
    h1.x = __float2half_rn(v.z); h1.y = __float2half_rn(v.w);
    l0.x = __float2half_rn(v.x - __half2float(h0.x));
    l0.y = __float2half_rn(v.y - __half2float(h0.y));
    l1.x = __float2half_rn(v.z - __half2float(h1.x));
    l1.y = __float2half_rn(v.w - __half2float(h1.y));
    __half2* d = (__half2*)(dst + row * 2 * K);
    int c2 = c4 * 2;
    int K2 = K >> 1;
    d[c2] = h0; d[c2 + 1] = h1;
    d[K2 + c2] = l0; d[K2 + c2 + 1] = l1;
}

// ---------------- W-split: src fp32 -> dst f16 hi only (flat) ----------------
__global__ void k_splitW(const float* __restrict__ src, __half* __restrict__ dst) {
    size_t i = (size_t)blockIdx.x * 256 + threadIdx.x;
    float4 v = ((const float4*)src)[i];
    __half2 h0, h1;
    h0.x = __float2half_rn(v.x); h0.y = __float2half_rn(v.y);
    h1.x = __float2half_rn(v.z); h1.y = __float2half_rn(v.w);
    __half2* d = (__half2*)dst;
    d[2 * i] = h0; d[2 * i + 1] = h1;
}

// ---------------- fp16 tensor-core GEMM, 4-stage cp.async ----------------
#define SPITCH 40
#define NSTG 4
template<int ACT, int OUT2>
__global__ void __launch_bounds__(256) k_gemm_f16(const __half* __restrict__ A,
                                                  const __half* __restrict__ W,
                                                  const float* __restrict__ bias,
                                                  void* __restrict__ Cout,
                                                  int N, int K) {
    __shared__ __align__(16) __half As[NSTG][128][SPITCH];
    __shared__ __align__(16) __half Ws[NSTG][128][SPITCH];
    int tid = threadIdx.x;
    int bm = blockIdx.y * 128, bn = blockIdx.x * 128;
    int lr = tid >> 1, lc = (tid & 1) * 16;
    int lane = tid & 31, wid = tid >> 5;
    int wm = (wid & 3) * 32, wn = (wid >> 2) * 64;
    int g = lane >> 2, t4 = lane & 3;
    int K2 = 2 * K;

    float c[2][8][4];
    #pragma unroll
    for (int mi = 0; mi < 2; mi++)
        #pragma unroll
        for (int ni = 0; ni < 8; ni++)
            #pragma unroll
            for (int q = 0; q < 4; q++) c[mi][ni][q] = 0.f;

    const __half* Aptr = A + (size_t)(bm + lr) * K2 + lc;
    int wr = bn + lr; if (wr >= N) wr = N - 1;
    const __half* Wrow = W + (size_t)wr * K + lc;

    uint32_t sbA = (uint32_t)__cvta_generic_to_shared(&As[0][0][0]);
    uint32_t sbW = (uint32_t)__cvta_generic_to_shared(&Ws[0][0][0]);
    const uint32_t bufStride = 128 * SPITCH * 2;
    uint32_t dOff = (uint32_t)((lr * SPITCH + lc) * 2);

    int l7 = lane & 7;
    int aRow = wm + ((lane >> 3) & 1) * 8 + l7;
    int aCol = (lane >> 4) * 8;
    int bRow = wn + (lane >> 4) * 8 + l7;
    int bCol = ((lane >> 3) & 1) * 8;

    int KT = K2 / 32;

    #pragma unroll
    for (int s = 0; s < NSTG - 1; s++) {
        if (s < KT) {
            int ao = s * 32;
            int wo = (ao >= K) ? ao - K : ao;
            const __half* ap = Aptr + ao;
            const __half* wp = Wrow + wo;
            uint32_t da = sbA + s * bufStride + dOff;
            uint32_t dw = sbW + s * bufStride + dOff;
            CP_ASYNC16(da, ap); CP_ASYNC16(da + 16, ap + 8);
            CP_ASYNC16(dw, wp); CP_ASYNC16(dw + 16, wp + 8);
        }
        CP_COMMIT();
    }

    for (int kt = 0; kt < KT; kt++) {
        CP_WAIT2();
        __syncthreads();

        int cur = kt & (NSTG - 1);
        uint32_t aBase = sbA + cur * bufStride;
        uint32_t wBase = sbW + cur * bufStride;
        #pragma unroll
        for (int kk = 0; kk < 32; kk += 16) {
            uint32_t af[2][4], bf[4][4];
            #pragma unroll
            for (int mi = 0; mi < 2; mi++) {
                uint32_t addr = aBase + (uint32_t)(((aRow + mi * 16) * SPITCH + aCol + kk) * 2);
                LDSM_X4(af[mi], addr);
            }
            #pragma unroll
            for (int q = 0; q < 4; q++) {
                uint32_t addr = wBase + (uint32_t)(((bRow + q * 16) * SPITCH + bCol + kk) * 2);
                LDSM_X4(bf[q], addr);
            }
            #pragma unroll
            for (int q = 0; q < 4; q++) {
                MMA_F16(c[0][2 * q],     af[0], bf[q][0], bf[q][1]);
                MMA_F16(c[1][2 * q],     af[1], bf[q][0], bf[q][1]);
                MMA_F16(c[0][2 * q + 1], af[0], bf[q][2], bf[q][3]);
                MMA_F16(c[1][2 * q + 1], af[1], bf[q][2], bf[q][3]);
            }
        }
        {
            int s = kt + NSTG - 1;
            if (s < KT) {
                int ao = s * 32;
                int wo = (ao >= K) ? ao - K : ao;
                const __half* ap = Aptr + ao;
                const __half* wp = Wrow + wo;
                uint32_t da = sbA + (s & (NSTG - 1)) * bufStride + dOff;
                uint32_t dw = sbW + (s & (NSTG - 1)) * bufStride + dOff;
                CP_ASYNC16(da, ap); CP_ASYNC16(da + 16, ap + 8);
                CP_ASYNC16(dw, wp); CP_ASYNC16(dw + 16, wp + 8);
            }
            CP_COMMIT();
        }
    }
    CP_WAIT0();

    #pragma unroll
    for (int mi = 0; mi < 2; mi++) {
        int r0 = bm + wm + mi * 16 + g;
        #pragma unroll
        for (int ni = 0; ni < 8; ni++) {
            int col = bn + wn + ni * 8 + 2 * t4;
            #pragma unroll
            for (int half = 0; half < 2; half++) {
                int r = r0 + half * 8;
                float v0 = c[mi][ni][half * 2 + 0];
                float v1 = c[mi][ni][half * 2 + 1];
                if (bias) { v0 += bias[col]; v1 += bias[col + 1]; }
                if (ACT == 1) {
                    v0 = 0.5f * v0 * (1.f + erff(v0 * 0.70710678118654752f));
                    v1 = 0.5f * v1 * (1.f + erff(v1 * 0.70710678118654752f));
                }
                if (OUT2) {
                    __half* O = (__half*)Cout;
                    __half2 hi, lo;
                    hi.x = __float2half_rn(v0); hi.y = __float2half_rn(v1);
                    lo.x = __float2half_rn(v0 - __half2float(hi.x));
                    lo.y = __float2half_rn(v1 - __half2float(hi.y));
                    size_t base = (size_t)r * 2 * N + col;
                    *(__half2*)&O[base]     = hi;
                    *(__half2*)&O[base + N] = lo;
                } else {
                    float* Cf = (float*)Cout;
                    if (col + 1 < N) {
                        float2 v; v.x = v0; v.y = v1;
                        *(float2*)&Cf[(size_t)r * N + col] = v;
                    } else if (col < N) {
                        Cf[(size_t)r * N + col] = v0;
                    }
                }
            }
        }
    }
}

// ---------------- k_G: per (b,c) G = C @ B^T (bf16 3-term); upper-tri warps skipped ----------------
#define GP 136
__global__ void __launch_bounds__(256) k_G() {
    extern __shared__ __align__(16) char sg[];
    __nv_bfloat16* Chi = (__nv_bfloat16*)sg;
    __nv_bfloat16* Clo = Chi + 128 * GP;
    __nv_bfloat16* Bhi = Clo + 128 * GP;
    __nv_bfloat16* Blo = Bhi + 128 * GP;
    int tid = threadIdx.x, lane = tid & 31, wid = tid >> 5;
    int blk = blockIdx.x;
    int base = blk * 128;
    int wm = (wid & 3) * 32, wn = (wid >> 2) * 64;
    int g = lane >> 2, t4 = lane & 3;

    for (int q = tid; q < 4096; q += 256) {
        int row = q >> 5, c4 = (q & 31) * 4;
        const float* rp = &g_xbc[(size_t)(base + row) * CONVDIM + DINNER];
        float4 vB = *(const float4*)(rp + c4);
        float4 vC = *(const float4*)(rp + DSTATE + c4);
        __nv_bfloat162 h, l;
        int o = row * GP + c4;
        h.x = __float2bfloat16_rn(vC.x); h.y = __float2bfloat16_rn(vC.y);
        l.x = __float2bfloat16_rn(vC.x - __bfloat162float(h.x));
        l.y = __float2bfloat16_rn(vC.y - __bfloat162float(h.y));
        *(__nv_bfloat162*)&Chi[o] = h; *(__nv_bfloat162*)&Clo[o] = l;
        h.x = __float2bfloat16_rn(vC.z); h.y = __float2bfloat16_rn(vC.w);
        l.x = __float2bfloat16_rn(vC.z - __bfloat162float(h.x));
        l.y = __float2bfloat16_rn(vC.w - __bfloat162float(h.y));
        *(__nv_bfloat162*)&Chi[o + 2] = h; *(__nv_bfloat162*)&Clo[o + 2] = l;
        h.x = __float2bfloat16_rn(vB.x); h.y = __float2bfloat16_rn(vB.y);
        l.x = __float2bfloat16_rn(vB.x - __bfloat162float(h.x));
        l.y = __float2bfloat16_rn(vB.y - __bfloat162float(h.y));
        *(__nv_bfloat162*)&Bhi[o] = h; *(__nv_bfloat162*)&Blo[o] = l;
        h.x = __float2bfloat16_rn(vB.z); h.y = __float2bfloat16_rn(vB.w);
        l.x = __float2bfloat16_rn(vB.z - __bfloat162float(h.x));
        l.y = __float2bfloat16_rn(vB.w - __bfloat162float(h.y));
        *(__nv_bfloat162*)&Bhi[o + 2] = h; *(__nv_bfloat162*)&Blo[o + 2] = l;
    }
    __syncthreads();

    if (wn > wm + 31) return;    // tile strictly above diagonal: G never read there

    uint32_t bChi = (uint32_t)__cvta_generic_to_shared(Chi);
    uint32_t bClo = (uint32_t)__cvta_generic_to_shared(Clo);
    uint32_t bBhi = (uint32_t)__cvta_generic_to_shared(Bhi);
    uint32_t bBlo = (uint32_t)__cvta_generic_to_shared(Blo);

    int l7 = lane & 7;
    int aRow = wm + ((lane >> 3) & 1) * 8 + l7;
    int aCol = (lane >> 4) * 8;
    int bRow = wn + (lane >> 4) * 8 + l7;
    int bCol = ((lane >> 3) & 1) * 8;

    float c[2][8][4];
    #pragma unroll
    for (int mi = 0; mi < 2; mi++)
        #pragma unroll
        for (int ni = 0; ni < 8; ni++)
            #pragma unroll
            for (int q = 0; q < 4; q++) c[mi][ni][q] = 0.f;

    #pragma unroll
    for (int term = 0; term < 3; term++) {
        uint32_t aB = (term == 2) ? bClo : bChi;
        uint32_t bB = (term == 1) ? bBlo : bBhi;
        #pragma unroll
        for (int kk = 0; kk < 128; kk += 16) {
            uint32_t af[2][4], bf[4][4];
            #pragma unroll
            for (int mi = 0; mi < 2; mi++) {
                uint32_t addr = aB + (uint32_t)(((aRow + mi * 16) * GP + aCol + kk) * 2);
                LDSM_X4(af[mi], addr);
            }
            #pragma unroll
            for (int q = 0; q < 4; q++) {
                uint32_t addr = bB + (uint32_t)(((bRow + q * 16) * GP + bCol + kk) * 2);
                LDSM_X4(bf[q], addr);
            }
            #pragma unroll
            for (int q = 0; q < 4; q++) {
                MMA_BF16(c[0][2 * q],     af[0], bf[q][0], bf[q][1]);
                MMA_BF16(c[1][2 * q],     af[1], bf[q][0], bf[q][1]);
                MMA_BF16(c[0][2 * q + 1], af[0], bf[q][2], bf[q][3]);
                MMA_BF16(c[1][2 * q + 1], af[1], bf[q][2], bf[q][3]);
            }
        }
    }

    float* Gout = &g_G[(size_t)blk * 16384];
    #pragma unroll
    for (int mi = 0; mi < 2; mi++) {
        int r0 = wm + mi * 16 + g;
        #pragma unroll
        for (int ni = 0; ni < 8; ni++) {
            int col = wn + ni * 8 + 2 * t4;
            #pragma unroll
            for (int half = 0; half < 2; half++) {
                int r = r0 + half * 8;
                float2 v; v.x = c[mi][ni][half * 2]; v.y = c[mi][ni][half * 2 + 1];
                *(float2*)&Gout[r * 128 + col] = v;
            }
        }
    }
}

// ---------------- shared MMA pass (2-term), k-loop bounded by kmax ----------------
#define BP 136
#define XP 72
template<int TRANSA>
__device__ __forceinline__ void ssd_pass(uint32_t aHi, uint32_t aLo, uint32_t xHi,
                                         int wm, int lane, int kmax, float cacc[8][4]) {
    int l7 = lane & 7;
    int aRow = wm + ((lane >> 3) & 1) * 8 + l7;
    int aCol = (lane >> 4) * 8;
    int tL = (lane >> 4) * 8 + l7;
    int tN = ((lane >> 3) & 1) * 8;
    int bL = ((lane >> 3) & 1) * 8 + l7;
    int bP = (lane >> 4) * 8;
    #pragma unroll
    for (int term = 0; term < 2; term++) {
        uint32_t aB = (term == 1) ? aLo : aHi;
        for (int k0 = 0; k0 < kmax; k0 += 16) {
            uint32_t af[4];
            if (TRANSA) {
                LDSM_X4T(af, aB + (uint32_t)(((k0 + tL) * BP + wm + tN) * 2));
            } else {
                LDSM_X4(af, aB + (uint32_t)((aRow * BP + k0 + aCol) * 2));
            }
            #pragma unroll
            for (int q = 0; q < 4; q++) {
                uint32_t bf[4];
                LDSM_X4T(bf, xHi + (uint32_t)(((k0 + bL) * XP + q * 16 + bP) * 2));
                MMA_F16(cacc[2 * q],     af, bf[0], bf[1]);
                MMA_F16(cacc[2 * q + 1], af, bf[2], bf[3]);
            }
        }
    }
}

// ---------------- causal depthwise conv1d + silu (4 s-positions/thread) ----------------
__global__ void k_conv(const float* __restrict__ conv_w, const float* __restrict__ conv_b) {
    int idx = blockIdx.x * 256 + threadIdx.x;
    int ch = idx % CONVDIM;
    int r  = idx / CONVDIM;
    int s4 = r % (SEQ / 4);
    int b  = r / (SEQ / 4);
    int s0 = s4 * 4;
    float w0 = conv_w[ch * 4], w1 = conv_w[ch * 4 + 1], w2 = conv_w[ch * 4 + 2], w3 = conv_w[ch * 4 + 3];
    float bias = conv_b[ch];
    float in[7];
    #pragma unroll
    for (int k = 0; k < 7; k++) {
        int sp = s0 + k - 3;
        in[k] = (sp >= 0) ? g_zx[(size_t)(b * SEQ + sp) * DINPROJ + DINNER + ch] : 0.f;
    }
    #pragma unroll
    for (int s = 0; s < 4; s++) {
        float acc = bias + in[s] * w0 + in[s + 1] * w1 + in[s + 2] * w2 + in[s + 3] * w3;
        acc = acc / (1.f + expf(-acc));
        g_xbc[(size_t)(b * SEQ + s0 + s) * CONVDIM + ch] = acc;
    }
}

// ---------------- dt softplus + per-chunk cumulative log-decay ----------------
__global__ void k_dtscan(const float* __restrict__ dt_bias, const float* __restrict__ A_log) {
    __shared__ float s[128];
    int blk = blockIdx.x, l = threadIdx.x;
    int h = blk & 15, c = (blk >> 4) & 15, b = blk >> 8;
    int tok = b * SEQ + c * CHUNK + l;
    float raw = g_zx[(size_t)tok * DINPROJ + 2304 + h] + dt_bias[h];
    float dtv = (raw > 20.f) ? raw : log1pf(expf(raw));
    float A = -expf(A_log[h]);
    g_dt[blk * 128 + l] = dtv;
    s[l] = dtv * A;
    __syncthreads();
    #pragma unroll
    for (int off = 1; off < 128; off <<= 1) {
        float t = (l >= off) ? s[l - off] : 0.f;
        __syncthreads();
        s[l] += t;
        __syncthreads();
    }
    g_acs[blk * 128 + l] = s[l];
}

// ---------------- per-chunk end states via tensor cores (2-term) ----------------
__global__ void __launch_bounds__(256) k_states() {
    extern __shared__ __align__(16) char sraw[];
    __half* Ahi = (__half*)sraw;
    __half* Alo = Ahi + 128 * BP;
    __half* Xhi = Alo + 128 * BP;
    float*  ws  = (float*)(Xhi + 128 * XP);
    int tid = threadIdx.x, lane = tid & 31, wid = tid >> 5;
    int blk = blockIdx.x;
    int h = blk & 15, cc = (blk >> 4) & 15, b = blk >> 8;
    int base = b * SEQ + cc * CHUNK;

    if (tid < 128) {
        float acsL = g_acs[blk * 128 + 127];
        ws[tid] = expf(acsL - g_acs[blk * 128 + tid]) * g_dt[blk * 128 + tid];
    }
    __syncthreads();
    for (int q = tid; q < 4096; q += 256) {
        int l = q >> 5, n4 = (q & 31) * 4;
        float4 v = *(const float4*)&g_xbc[(size_t)(base + l) * CONVDIM + DINNER + n4];
        float w = ws[l];
        v.x *= w; v.y *= w; v.z *= w; v.w *= w;
        split4(v, Ahi, Alo, l * BP + n4);
    }
    for (int q = tid; q < 2048; q += 256) {
        int l = q >> 4, p4 = (q & 15) * 4;
        float4 v = *(const float4*)&g_xbc[(size_t)(base + l) * CONVDIM + h * 64 + p4];
        hi4(v, Xhi, l * XP + p4);
    }
    __syncthreads();

    uint32_t bAhi = (uint32_t)__cvta_generic_to_shared(Ahi);
    uint32_t bAlo = (uint32_t)__cvta_generic_to_shared(Alo);
    uint32_t bXhi = (uint32_t)__cvta_generic_to_shared(Xhi);
    int wm = wid * 16;
    float cacc[8][4];
    #pragma unroll
    for (int ni = 0; ni < 8; ni++)
        #pragma unroll
        for (int q = 0; q < 4; q++) cacc[ni][q] = 0.f;

    ssd_pass<1>(bAhi, bAlo, bXhi, wm, lane, 128, cacc);

    int g = lane >> 2, t4 = lane & 3;
    float* d0 = &g_states[(size_t)blk * 8192 + (wm + g) * 64];
    float* d1 = d0 + 8 * 64;
    #pragma unroll
    for (int ni = 0; ni < 8; ni++) {
        int col = ni * 8 + 2 * t4;
        float2 v0; v0.x = cacc[ni][0]; v0.y = cacc[ni][1];
        float2 v1; v1.x = cacc[ni][2]; v1.y = cacc[ni][3];
        *(float2*)&d0[col] = v0;
        *(float2*)&d1[col] = v1;
    }
}

// ---------------- sequential chunk scan ----------------
__global__ void k_scan() {
    int bx = blockIdx.x;
    int e8 = bx & 7;
    int bh = bx >> 3;
    int b = bh >> 4, h = bh & 15;
    int e = e8 * 1024 + threadIdx.x;
    for (int k = 0; k < 4; k++, e += 256) {
        float acc = 0.f;
        #pragma unroll
        for (int c = 0; c < NCHUNK; c++) {
            int blk = ((b * NCHUNK + c) << 4) + h;
            g_prev[(size_t)blk * 8192 + e] = acc;
            float cd = expf(g_acs[blk * 128 + 127]);
            acc = cd * acc + g_states[(size_t)blk * 8192 + e];
        }
    }
}

// ---------------- fused SSD output via tensor cores; causal k-bound in pass 1 ----------------
__global__ void __launch_bounds__(256) k_y(const float* __restrict__ D_head) {
    extern __shared__ __align__(16) char sraw[];
    __half* Ahi = (__half*)sraw;
    __half* Alo = Ahi + 128 * BP;
    __half* Xhi = Alo + 128 * BP;
    float* acs_s = (float*)(Xhi + 128 * XP);
    float* dt_s  = acs_s + 128;
    int tid = threadIdx.x, lane = tid & 31, wid = tid >> 5;
    int blk = blockIdx.x;
    int h = blk & 15, cc = (blk >> 4) & 15, b = blk >> 8;
    int base = b * SEQ + cc * CHUNK;
    size_t gbase = (size_t)(blk >> 4) * 16384;

    if (tid < 128) {
        acs_s[tid] = g_acs[blk * 128 + tid];
        dt_s[tid]  = g_dt[blk * 128 + tid];
    }
    __syncthreads();

    // build M and x
    for (int q = tid; q < 4096; q += 256) {
        int i = q >> 5, j4 = (q & 31) * 4;
        float ai = acs_s[i];
        float4 m;
        if (j4 + 3 <= i) {
            float4 gv = *(const float4*)&g_G[gbase + i * 128 + j4];
            m.x = expf(ai - acs_s[j4])     * dt_s[j4]     * gv.x;
            m.y = expf(ai - acs_s[j4 + 1]) * dt_s[j4 + 1] * gv.y;
            m.z = expf(ai - acs_s[j4 + 2]) * dt_s[j4 + 2] * gv.z;
            m.w = expf(ai - acs_s[j4 + 3]) * dt_s[j4 + 3] * gv.w;
        } else if (j4 <= i) {
            float4 gv = *(const float4*)&g_G[gbase + i * 128 + j4];
            m.x = (j4     <= i) ? expf(ai - acs_s[j4])     * dt_s[j4]     * gv.x : 0.f;
            m.y = (j4 + 1 <= i) ? expf(ai - acs_s[j4 + 1]) * dt_s[j4 + 1] * gv.y : 0.f;
            m.z = (j4 + 2 <= i) ? expf(ai - acs_s[j4 + 2]) * dt_s[j4 + 2] * gv.z : 0.f;
            m.w = (j4 + 3 <= i) ? expf(ai - acs_s[j4 + 3]) * dt_s[j4 + 3] * gv.w : 0.f;
        } else {
            m = make_float4(0.f, 0.f, 0.f, 0.f);
        }
        split4(m, Ahi, Alo, i * BP + j4);
    }
    for (int q = tid; q < 2048; q += 256) {
        int l = q >> 4, p4 = (q & 15) * 4;
        float4 v = *(const float4*)&g_xbc[(size_t)(base + l) * CONVDIM + h * 64 + p4];
        hi4(v, Xhi, l * XP + p4);
    }
    __syncthreads();

    uint32_t bAhi = (uint32_t)__cvta_generic_to_shared(Ahi);
    uint32_t bAlo = (uint32_t)__cvta_generic_to_shared(Alo);
    uint32_t bXhi = (uint32_t)__cvta_generic_to_shared(Xhi);
    int wm = wid * 16;
    float cacc[8][4];
    #pragma unroll
    for (int ni = 0; ni < 8; ni++)
        #pragma unroll
        for (int q = 0; q < 4; q++) cacc[ni][q] = 0.f;

    // pass 1: Y_diag — M rows [wm, wm+16) have support only for j < wm+16
    ssd_pass<0>(bAhi, bAlo, bXhi, wm, lane, wm + 16, cacc);

    // D*x from resident x hi
    int g = lane >> 2, t4 = lane & 3;
    {
        float dh = D_head[h];
        int i0 = wm + g, i1 = i0 + 8;
        #pragma unroll
        for (int ni = 0; ni < 8; ni++) {
            int col = ni * 8 + 2 * t4;
            cacc[ni][0] += dh * __half2float(Xhi[i0 * XP + col]);
            cacc[ni][1] += dh * __half2float(Xhi[i0 * XP + col + 1]);
            cacc[ni][2] += dh * __half2float(Xhi[i1 * XP + col]);
            cacc[ni][3] += dh * __half2float(Xhi[i1 * XP + col + 1]);
        }
    }
    __syncthreads();

    // rebuild: A = C~, X = prev
    for (int q = tid; q < 4096; q += 256) {
        int i = q >> 5, n4 = (q & 31) * 4;
        float4 v = *(const float4*)&g_xbc[(size_t)(base + i) * CONVDIM + DINNER + DSTATE + n4];
        float e = expf(acs_s[i]);
        v.x *= e; v.y *= e; v.z *= e; v.w *= e;
        split4(v, Ahi, Alo, i * BP + n4);
    }
    for (int q = tid; q < 2048; q += 256) {
        int n = q >> 4, p4 = (q & 15) * 4;
        float4 v = *(const float4*)&g_prev[(size_t)blk * 8192 + n * 64 + p4];
        hi4(v, Xhi, n * XP + p4);
    }
    __syncthreads();

    // pass 2: Y_off (full K)
    ssd_pass<0>(bAhi, bAlo, bXhi, wm, lane, 128, cacc);

    // epilogue
    {
        int i0 = wm + g;
        float* d0 = &g_y[(size_t)(base + i0) * DINNER + h * 64];
        float* d1 = &g_y[(size_t)(base + i0 + 8) * DINNER + h * 64];
        #pragma unroll
        for (int ni = 0; ni < 8; ni++) {
            int col = ni * 8 + 2 * t4;
            float2 v0; v0.x = cacc[ni][0]; v0.y = cacc[ni][1];
            float2 v1; v1.x = cacc[ni][2]; v1.y = cacc[ni][3];
            *(float2*)&d0[col] = v0;
            *(float2*)&d1[col] = v1;
        }
    }
}

// ---------------- gate with silu(z) + RMSNorm * norm_w -> fp16 [hi|lo] ----------------
__global__ void k_gate(const float* __restrict__ norm_w, __half* __restrict__ out2) {
    __shared__ float red[64];
    int t = blockIdx.x, tid = threadIdx.x;
    float v[4]; float ss = 0.f, dummy = 0.f;
    #pragma unroll
    for (int k = 0; k < 4; k++) {
        int d = tid + k * 256;
        float yv = g_y[(size_t)t * DINNER + d];
        float zv = g_zx[(size_t)t * DINPROJ + d];
        float sv = yv * (zv / (1.f + expf(-zv)));
        v[k] = sv; ss += sv * sv;
    }
    blockReduce2(ss, dummy, red);
    float sc = rsqrtf(ss * (1.f / 1024.f) + EPSF);
    __half* row = out2 + (size_t)t * 2 * DINNER;
    #pragma unroll
    for (int k = 0; k < 4; k++) {
        int d = tid + k * 256;
        f16x2_store_scalar(row, DINNER, d, v[k] * sc * norm_w[d]);
    }
}

// ---------------- out = LayerNorm(a + b) * w + beta, optional fp16 [hi|lo] copy ----------------
__global__ void k_addln(const float* __restrict__ a, const float* __restrict__ bsrc,
                        const float* __restrict__ w, const float* __restrict__ beta,
                        float* __restrict__ o, __half* __restrict__ out2) {
    __shared__ float red[64];
    int t = blockIdx.x, tid = threadIdx.x;
    float v[4]; float s = 0.f, ssq = 0.f;
    #pragma unroll
    for (int k = 0; k < 4; k++) {
        int d = tid + k * 128;
        float x = a[(size_t)t * DMODEL + d] + bsrc[(size_t)t * DMODEL + d];
        v[k] = x; s += x; ssq += x * x;
    }
    blockReduce2(s, ssq, red);
    float mean = s * (1.f / 512.f);
    float var = ssq * (1.f / 512.f) - mean * mean;
    float inv = rsqrtf(var + EPSF);
    #pragma unroll
    for (int k = 0; k < 4; k++) {
        int d = tid + k * 128;
        float r = (v[k] - mean) * inv * w[d] + beta[d];
        o[(size_t)t * DMODEL + d] = r;
        if (out2) f16x2_store_scalar(out2 + (size_t)t * 2 * DMODEL, DMODEL, d, r);
    }
}

// ---------------- launch ----------------
extern "C" void kernel_launch(void* const* d_in, const int* in_sizes, int n_in,
                              void* d_out, int out_size) {
    const float* tgt        = (const float*)d_in[0];
    const float* in_proj_w  = (const float*)d_in[5];
    const float* conv_w     = (const float*)d_in[6];
    const float* conv_b     = (const float*)d_in[7];
    const float* dt_bias    = (const float*)d_in[8];
    const float* A_log      = (const float*)d_in[9];
    const float* D_head     = (const float*)d_in[10];
    const float* norm_w     = (const float*)d_in[11];
    const float* out_proj_w = (const float*)d_in[12];
    const float* n1w = (const float*)d_in[13];
    const float* n1b = (const float*)d_in[14];
    const float* w1  = (const float*)d_in[15];
    const float* b1  = (const float*)d_in[16];
    const float* w2  = (const float*)d_in[17];
    const float* b2  = (const float*)d_in[18];
    const float* n3w = (const float*)d_in[19];
    const float* n3b = (const float*)d_in[20];
    float* out = (float*)d_out;

    float *zx, *mo, *tb, *f2;
    __half *A2, *A2b, *W2;
    cudaGetSymbolAddress((void**)&zx,   g_zx);
    cudaGetSymbolAddress((void**)&mo,   g_mo);
    cudaGetSymbolAddress((void**)&tb,   g_t);
    cudaGetSymbolAddress((void**)&f2,   g_f2);
    cudaGetSymbolAddress((void**)&A2,   g_A2);
    cudaGetSymbolAddress((void**)&A2b,  g_A2b);
    cudaGetSymbolAddress((void**)&W2,   g_W2);

    const int smem_st = (2 * 128 * BP + 128 * XP) * 2 + 512;
    const int smem_y  = (2 * 128 * BP + 128 * XP) * 2 + 1024;
    const int smem_g  = 4 * 128 * GP * 2;
    cudaFuncSetAttribute(k_states, cudaFuncAttributeMaxDynamicSharedMemorySize, smem_st);
    cudaFuncSetAttribute(k_y,      cudaFuncAttributeMaxDynamicSharedMemorySize, smem_y);
    cudaFuncSetAttribute(k_G,      cudaFuncAttributeMaxDynamicSharedMemorySize, smem_g);

    // 1. in_proj: zx = tgt @ in_proj_w^T
    k_splitA<<<(int)(((size_t)TOK * DMODEL / 4) / 256), 256>>>(tgt, A2, DMODEL);
    k_splitW<<<(DINPROJ * DMODEL / 4) / 256, 256>>>(in_proj_w, W2);
    k_gemm_f16<0, 0><<<dim3((DINPROJ + 127) / 128, TOK / 128), 256>>>(A2, W2, nullptr, zx, DINPROJ, DMODEL);
    // 2. conv + silu
    k_conv<<<(TOK / 4 * CONVDIM) / 256, 256>>>(conv_w, conv_b);
    // 3. dt softplus + cumsum
    k_dtscan<<<NBLK, 128>>>(dt_bias, A_log);
    // 4. shared score matrices G = C @ B^T
    k_G<<<NGC, 256, smem_g>>>();
    // 5. chunk end-states (tensor core)
    k_states<<<NBLK, 256, smem_st>>>();
    // 6. chunk scan -> prev
    k_scan<<<BATCH * NHEADS * 8, 256>>>();
    // 7. fused SSD output (tensor core, causal-bounded)
    k_y<<<NBLK, 256, smem_y>>>(D_head);
    // 8. gate + rmsnorm -> fp16 [hi|lo]
    k_gate<<<TOK, 256>>>(norm_w, A2);
    // 9. out_proj
    k_splitW<<<(DMODEL * DINNER / 4) / 256, 256>>>(out_proj_w, W2);
    k_gemm_f16<0, 0><<<dim3(DMODEL / 128, TOK / 128), 256>>>(A2, W2, nullptr, mo, DMODEL, DINNER);
    // 10. t = LN(tgt + mo), emit fp16 [hi|lo]
    k_addln<<<TOK, 128>>>(tgt, mo, n1w, n1b, tb, A2);
    // 11. f1 = gelu(t @ w1^T + b1) -> fp16 [hi|lo]
    k_splitW<<<(FF * DMODEL / 4) / 256, 256>>>(w1, W2);
    k_gemm_f16<1, 1><<<dim3(FF / 128, TOK / 128), 256>>>(A2, W2, b1, A2b, FF, DMODEL);
    // 12. f2 = f1 @ w2^T + b2
    k_splitW<<<(DMODEL * FF / 4) / 256, 256>>>(w2, W2);
    k_gemm_f16<0, 0><<<dim3(DMODEL / 128, TOK / 128), 256>>>(A2b, W2, b2, f2, DMODEL, FF);
    // 13. out = LN(t + f2)
    k_addln<<<TOK, 128>>>(tb, f2, n3w, n3b, out, nullptr);
}

// round 17
// speedup vs baseline: 1.1588x; 1.1588x over previous
#include <cuda_runtime.h>
#include <cuda_bf16.h>
#include <cuda_fp16.h>
#include <math.h>
#include <cstdint>

// ---------------- problem constants ----------------
#define BATCH 8
#define SEQ 2048
#define TOK (BATCH*SEQ)          // 16384
#define DMODEL 512
#define DINNER 1024
#define DSTATE 128
#define NHEADS 16
#define HEADDIM 64
#define CONVDIM 1280
#define DINPROJ 2320
#define FF 2048
#define CHUNK 128
#define NCHUNK (SEQ/CHUNK)       // 16
#define NBLK (BATCH*NCHUNK*NHEADS) // 2048
#define NGC (BATCH*NCHUNK)       // 128
#define EPSF 1e-5f

#define MMA_F16(cc, aa, b0, b1) \
    asm volatile("mma.sync.aligned.m16n8k16.row.col.f32.f16.f16.f32 " \
        "{%0,%1,%2,%3},{%4,%5,%6,%7},{%8,%9},{%0,%1,%2,%3};" \
        : "+f"(cc[0]), "+f"(cc[1]), "+f"(cc[2]), "+f"(cc[3]) \
        : "r"(aa[0]), "r"(aa[1]), "r"(aa[2]), "r"(aa[3]), "r"(b0), "r"(b1))

#define MMA_BF16(cc, aa, b0, b1) \
    asm volatile("mma.sync.aligned.m16n8k16.row.col.f32.bf16.bf16.f32 " \
        "{%0,%1,%2,%3},{%4,%5,%6,%7},{%8,%9},{%0,%1,%2,%3};" \
        : "+f"(cc[0]), "+f"(cc[1]), "+f"(cc[2]), "+f"(cc[3]) \
        : "r"(aa[0]), "r"(aa[1]), "r"(aa[2]), "r"(aa[3]), "r"(b0), "r"(b1))

#define LDSM_X4(r, addr) \
    asm volatile("ldmatrix.sync.aligned.m8n8.x4.shared.b16 {%0,%1,%2,%3},[%4];" \
        : "=r"((r)[0]), "=r"((r)[1]), "=r"((r)[2]), "=r"((r)[3]) : "r"(addr))

#define LDSM_X4T(r, addr) \
    asm volatile("ldmatrix.sync.aligned.m8n8.x4.trans.shared.b16 {%0,%1,%2,%3},[%4];" \
        : "=r"((r)[0]), "=r"((r)[1]), "=r"((r)[2]), "=r"((r)[3]) : "r"(addr))

#define CP_ASYNC16(dst, src) \
    asm volatile("cp.async.cg.shared.global [%0], [%1], 16;" :: "r"(dst), "l"(src))
#define CP_COMMIT() asm volatile("cp.async.commit_group;" ::: "memory")
#define CP_WAIT2()  asm volatile("cp.async.wait_group 2;" ::: "memory")
#define CP_WAIT0()  asm volatile("cp.async.wait_group 0;" ::: "memory")

// ---------------- scratch ----------------
__device__ __align__(16) float g_zx[TOK*DINPROJ];
__device__ __align__(16) float g_xbc[TOK*CONVDIM];
__device__ __align__(16) float g_dt[NBLK*CHUNK];
__device__ __align__(16) float g_acs[NBLK*CHUNK];
__device__ __align__(16) float g_states[(size_t)NBLK*DSTATE*HEADDIM];
__device__ __align__(16) float g_prev[(size_t)NBLK*DSTATE*HEADDIM];
__device__ __align__(16) float g_y[(size_t)TOK*DINNER];
__device__ __align__(16) float g_mo[(size_t)TOK*DMODEL];
__device__ __align__(16) float g_t[(size_t)TOK*DMODEL];
__device__ __align__(16) float g_f2[(size_t)TOK*DMODEL];
__device__ __align__(16) float g_G[(size_t)NGC*CHUNK*CHUNK];
// fp16 operands: A side [hi|lo] pitch 2K, W side [hi] pitch K
__device__ __align__(16) __half g_A2[(size_t)TOK*2*DINNER];
__device__ __align__(16) __half g_A2b[(size_t)TOK*2*FF];
__device__ __align__(16) __half g_W2[DINPROJ*DMODEL];

// ---------------- helpers ----------------
__device__ __forceinline__ void blockReduce2(float& a, float& b, float* sh) {
    int lane = threadIdx.x & 31, w = threadIdx.x >> 5;
    #pragma unroll
    for (int o = 16; o; o >>= 1) {
        a += __shfl_xor_sync(0xffffffffu, a, o);
        b += __shfl_xor_sync(0xffffffffu, b, o);
    }
    if (lane == 0) { sh[w] = a; sh[32 + w] = b; }
    __syncthreads();
    int nw = blockDim.x >> 5;
    if (w == 0) {
        a = (lane < nw) ? sh[lane] : 0.f;
        b = (lane < nw) ? sh[32 + lane] : 0.f;
        #pragma unroll
        for (int o = 16; o; o >>= 1) {
            a += __shfl_xor_sync(0xffffffffu, a, o);
            b += __shfl_xor_sync(0xffffffffu, b, o);
        }
        if (lane == 0) { sh[0] = a; sh[32] = b; }
    }
    __syncthreads();
    a = sh[0]; b = sh[32];
}

__device__ __forceinline__ void f16x2_store_scalar(__half* row, int K, int d, float s) {
    __half hi = __float2half_rn(s);
    __half lo = __float2half_rn(s - __half2float(hi));
    row[d] = hi; row[K + d] = lo;
}

__device__ __forceinline__ void split4(float4 v, __half* hi, __half* lo, int o) {
    __half2 h0, h1, l0, l1;
    h0.x = __float2half_rn(v.x); h0.y = __float2half_rn(v.y);
    h1.x = __float2half_rn(v.z); h1.y = __float2half_rn(v.w);
    l0.x = __float2half_rn(v.x - __half2float(h0.x));
    l0.y = __float2half_rn(v.y - __half2float(h0.y));
    l1.x = __float2half_rn(v.z - __half2float(h1.x));
    l1.y = __float2half_rn(v.w - __half2float(h1.y));
    *(__half2*)&hi[o] = h0; *(__half2*)&hi[o + 2] = h1;
    *(__half2*)&lo[o] = l0; *(__half2*)&lo[o + 2] = l1;
}

__device__ __forceinline__ void hi4(float4 v, __half* hi, int o) {
    __half2 h0, h1;
    h0.x = __float2half_rn(v.x); h0.y = __float2half_rn(v.y);
    h1.x = __float2half_rn(v.z); h1.y = __float2half_rn(v.w);
    *(__half2*)&hi[o] = h0; *(__half2*)&hi[o + 2] = h1;
}

// ---------------- A-split: src[M,K] fp32 -> dst[M,2K] f16 (hi | lo) ----------------
__global__ void k_splitA(const float* __restrict__ src, __half* __restrict__ dst, int K) {
    size_t i = (size_t)blockIdx.x * 256 + threadIdx.x;
    int K4 = K >> 2;
    size_t row = i / K4;
    int c4 = (int)(i % K4);
    float4 v = ((const float4*)src)[i];
    __half2 h0, h1, l0, l1;
    h0.x = __float2half_rn(v.x); h0.y = __float2half_rn(v.y);
    h1.x = __float2half_rn(v.z); h1.y = __float2half_rn(v.w);
    l0.x = __float2half_rn(v.x - __half2float(h0.x));
    l0.y = __float2half_rn(v.y - __half2float(h0.y));
    l1.x = __float2half_rn(v.z - __half2float(h1.x));
    l1.y = __float2half_rn(v.w - __half2float(h1.y));
    __half2* d = (__half2*)(dst + row * 2 * K);
    int c2 = c4 * 2;
    int K2 = K >> 1;
    d[c2] = h0; d[c2 + 1] = h1;
    d[K2 + c2] = l0; d[K2 + c2 + 1] = l1;
}

// ---------------- W-split: src fp32 -> dst f16 hi only (flat) ----------------
__global__ void k_splitW(const float* __restrict__ src, __half* __restrict__ dst) {
    size_t i = (size_t)blockIdx.x * 256 + threadIdx.x;
    float4 v = ((const float4*)src)[i];
    __half2 h0, h1;
    h0.x = __float2half_rn(v.x); h0.y = __float2half_rn(v.y);
    h1.x = __float2half_rn(v.z); h1.y = __float2half_rn(v.w);
    __half2* d = (__half2*)dst;
    d[2 * i] = h0; d[2 * i + 1] = h1;
}

// ---------------- fp16 tensor-core GEMM, 4-stage cp.async ----------------
#define SPITCH 40
#define NSTG 4
template<int ACT, int OUT2>
__global__ void __launch_bounds__(256) k_gemm_f16(const __half* __restrict__ A,
                                                  const __half* __restrict__ W,
                                                  const float* __restrict__ bias,
                                                  void* __restrict__ Cout,
                                                  int N, int K) {
    __shared__ __align__(16) __half As[NSTG][128][SPITCH];
    __shared__ __align__(16) __half Ws[NSTG][128][SPITCH];
    int tid = threadIdx.x;
    int bm = blockIdx.y * 128, bn = blockIdx.x * 128;
    int lr = tid >> 1, lc = (tid & 1) * 16;
    int lane = tid & 31, wid = tid >> 5;
    int wm = (wid & 3) * 32, wn = (wid >> 2) * 64;
    int g = lane >> 2, t4 = lane & 3;
    int K2 = 2 * K;

    float c[2][8][4];
    #pragma unroll
    for (int mi = 0; mi < 2; mi++)
        #pragma unroll
        for (int ni = 0; ni < 8; ni++)
            #pragma unroll
            for (int q = 0; q < 4; q++) c[mi][ni][q] = 0.f;

    const __half* Aptr = A + (size_t)(bm + lr) * K2 + lc;
    int wr = bn + lr; if (wr >= N) wr = N - 1;
    const __half* Wrow = W + (size_t)wr * K + lc;

    uint32_t sbA = (uint32_t)__cvta_generic_to_shared(&As[0][0][0]);
    uint32_t sbW = (uint32_t)__cvta_generic_to_shared(&Ws[0][0][0]);
    const uint32_t bufStride = 128 * SPITCH * 2;
    uint32_t dOff = (uint32_t)((lr * SPITCH + lc) * 2);

    int l7 = lane & 7;
    int aRow = wm + ((lane >> 3) & 1) * 8 + l7;
    int aCol = (lane >> 4) * 8;
    int bRow = wn + (lane >> 4) * 8 + l7;
    int bCol = ((lane >> 3) & 1) * 8;

    int KT = K2 / 32;

    #pragma unroll
    for (int s = 0; s < NSTG - 1; s++) {
        if (s < KT) {
            int ao = s * 32;
            int wo = (ao >= K) ? ao - K : ao;
            const __half* ap = Aptr + ao;
            const __half* wp = Wrow + wo;
            uint32_t da = sbA + s * bufStride + dOff;
            uint32_t dw = sbW + s * bufStride + dOff;
            CP_ASYNC16(da, ap); CP_ASYNC16(da + 16, ap + 8);
            CP_ASYNC16(dw, wp); CP_ASYNC16(dw + 16, wp + 8);
        }
        CP_COMMIT();
    }

    for (int kt = 0; kt < KT; kt++) {
        CP_WAIT2();
        __syncthreads();

        int cur = kt & (NSTG - 1);
        uint32_t aBase = sbA + cur * bufStride;
        uint32_t wBase = sbW + cur * bufStride;
        #pragma unroll
        for (int kk = 0; kk < 32; kk += 16) {
            uint32_t af[2][4], bf[4][4];
            #pragma unroll
            for (int mi = 0; mi < 2; mi++) {
                uint32_t addr = aBase + (uint32_t)(((aRow + mi * 16) * SPITCH + aCol + kk) * 2);
                LDSM_X4(af[mi], addr);
            }
            #pragma unroll
            for (int q = 0; q < 4; q++) {
                uint32_t addr = wBase + (uint32_t)(((bRow + q * 16) * SPITCH + bCol + kk) * 2);
                LDSM_X4(bf[q], addr);
            }
            #pragma unroll
            for (int q = 0; q < 4; q++) {
                MMA_F16(c[0][2 * q],     af[0], bf[q][0], bf[q][1]);
                MMA_F16(c[1][2 * q],     af[1], bf[q][0], bf[q][1]);
                MMA_F16(c[0][2 * q + 1], af[0], bf[q][2], bf[q][3]);
                MMA_F16(c[1][2 * q + 1], af[1], bf[q][2], bf[q][3]);
            }
        }
        {
            int s = kt + NSTG - 1;
            if (s < KT) {
                int ao = s * 32;
                int wo = (ao >= K) ? ao - K : ao;
                const __half* ap = Aptr + ao;
                const __half* wp = Wrow + wo;
                uint32_t da = sbA + (s & (NSTG - 1)) * bufStride + dOff;
                uint32_t dw = sbW + (s & (NSTG - 1)) * bufStride + dOff;
                CP_ASYNC16(da, ap); CP_ASYNC16(da + 16, ap + 8);
                CP_ASYNC16(dw, wp); CP_ASYNC16(dw + 16, wp + 8);
            }
            CP_COMMIT();
        }
    }
    CP_WAIT0();

    #pragma unroll
    for (int mi = 0; mi < 2; mi++) {
        int r0 = bm + wm + mi * 16 + g;
        #pragma unroll
        for (int ni = 0; ni < 8; ni++) {
            int col = bn + wn + ni * 8 + 2 * t4;
            #pragma unroll
            for (int half = 0; half < 2; half++) {
                int r = r0 + half * 8;
                float v0 = c[mi][ni][half * 2 + 0];
                float v1 = c[mi][ni][half * 2 + 1];
                if (bias) { v0 += bias[col]; v1 += bias[col + 1]; }
                if (ACT == 1) {
                    v0 = 0.5f * v0 * (1.f + erff(v0 * 0.70710678118654752f));
                    v1 = 0.5f * v1 * (1.f + erff(v1 * 0.70710678118654752f));
                }
                if (OUT2) {
                    __half* O = (__half*)Cout;
                    __half2 hi, lo;
                    hi.x = __float2half_rn(v0); hi.y = __float2half_rn(v1);
                    lo.x = __float2half_rn(v0 - __half2float(hi.x));
                    lo.y = __float2half_rn(v1 - __half2float(hi.y));
                    size_t base = (size_t)r * 2 * N + col;
                    *(__half2*)&O[base]     = hi;
                    *(__half2*)&O[base + N] = lo;
                } else {
                    float* Cf = (float*)Cout;
                    if (col + 1 < N) {
                        float2 v; v.x = v0; v.y = v1;
                        *(float2*)&Cf[(size_t)r * N + col] = v;
                    } else if (col < N) {
                        Cf[(size_t)r * N + col] = v0;
                    }
                }
            }
        }
    }
}

// ---------------- k_G: per (b,c) G = C @ B^T (bf16 3-term); upper-tri warps skipped ----------------
#define GP 136
__global__ void __launch_bounds__(256) k_G() {
    extern __shared__ __align__(16) char sg[];
    __nv_bfloat16* Chi = (__nv_bfloat16*)sg;
    __nv_bfloat16* Clo = Chi + 128 * GP;
    __nv_bfloat16* Bhi = Clo + 128 * GP;
    __nv_bfloat16* Blo = Bhi + 128 * GP;
    int tid = threadIdx.x, lane = tid & 31, wid = tid >> 5;
    int blk = blockIdx.x;
    int base = blk * 128;
    int wm = (wid & 3) * 32, wn = (wid >> 2) * 64;
    int g = lane >> 2, t4 = lane & 3;

    for (int q = tid; q < 4096; q += 256) {
        int row = q >> 5, c4 = (q & 31) * 4;
        const float* rp = &g_xbc[(size_t)(base + row) * CONVDIM + DINNER];
        float4 vB = *(const float4*)(rp + c4);
        float4 vC = *(const float4*)(rp + DSTATE + c4);
        __nv_bfloat162 h, l;
        int o = row * GP + c4;
        h.x = __float2bfloat16_rn(vC.x); h.y = __float2bfloat16_rn(vC.y);
        l.x = __float2bfloat16_rn(vC.x - __bfloat162float(h.x));
        l.y = __float2bfloat16_rn(vC.y - __bfloat162float(h.y));
        *(__nv_bfloat162*)&Chi[o] = h; *(__nv_bfloat162*)&Clo[o] = l;
        h.x = __float2bfloat16_rn(vC.z); h.y = __float2bfloat16_rn(vC.w);
        l.x = __float2bfloat16_rn(vC.z - __bfloat162float(h.x));
        l.y = __float2bfloat16_rn(vC.w - __bfloat162float(h.y));
        *(__nv_bfloat162*)&Chi[o + 2] = h; *(__nv_bfloat162*)&Clo[o + 2] = l;
        h.x = __float2bfloat16_rn(vB.x); h.y = __float2bfloat16_rn(vB.y);
        l.x = __float2bfloat16_rn(vB.x - __bfloat162float(h.x));
        l.y = __float2bfloat16_rn(vB.y - __bfloat162float(h.y));
        *(__nv_bfloat162*)&Bhi[o] = h; *(__nv_bfloat162*)&Blo[o] = l;
        h.x = __float2bfloat16_rn(vB.z); h.y = __float2bfloat16_rn(vB.w);
        l.x = __float2bfloat16_rn(vB.z - __bfloat162float(h.x));
        l.y = __float2bfloat16_rn(vB.w - __bfloat162float(h.y));
        *(__nv_bfloat162*)&Bhi[o + 2] = h; *(__nv_bfloat162*)&Blo[o + 2] = l;
    }
    __syncthreads();

    if (wn > wm + 31) return;    // tile strictly above diagonal: never read

    uint32_t bChi = (uint32_t)__cvta_generic_to_shared(Chi);
    uint32_t bClo = (uint32_t)__cvta_generic_to_shared(Clo);
    uint32_t bBhi = (uint32_t)__cvta_generic_to_shared(Bhi);
    uint32_t bBlo = (uint32_t)__cvta_generic_to_shared(Blo);

    int l7 = lane & 7;
    int aRow = wm + ((lane >> 3) & 1) * 8 + l7;
    int aCol = (lane >> 4) * 8;
    int bRow = wn + (lane >> 4) * 8 + l7;
    int bCol = ((lane >> 3) & 1) * 8;

    float c[2][8][4];
    #pragma unroll
    for (int mi = 0; mi < 2; mi++)
        #pragma unroll
        for (int ni = 0; ni < 8; ni++)
            #pragma unroll
            for (int q = 0; q < 4; q++) c[mi][ni][q] = 0.f;

    #pragma unroll
    for (int term = 0; term < 3; term++) {
        uint32_t aB = (term == 2) ? bClo : bChi;
        uint32_t bB = (term == 1) ? bBlo : bBhi;
        #pragma unroll
        for (int kk = 0; kk < 128; kk += 16) {
            uint32_t af[2][4], bf[4][4];
            #pragma unroll
            for (int mi = 0; mi < 2; mi++) {
                uint32_t addr = aB + (uint32_t)(((aRow + mi * 16) * GP + aCol + kk) * 2);
                LDSM_X4(af[mi], addr);
            }
            #pragma unroll
            for (int q = 0; q < 4; q++) {
                uint32_t addr = bB + (uint32_t)(((bRow + q * 16) * GP + bCol + kk) * 2);
                LDSM_X4(bf[q], addr);
            }
            #pragma unroll
            for (int q = 0; q < 4; q++) {
                MMA_BF16(c[0][2 * q],     af[0], bf[q][0], bf[q][1]);
                MMA_BF16(c[1][2 * q],     af[1], bf[q][0], bf[q][1]);
                MMA_BF16(c[0][2 * q + 1], af[0], bf[q][2], bf[q][3]);
                MMA_BF16(c[1][2 * q + 1], af[1], bf[q][2], bf[q][3]);
            }
        }
    }

    float* Gout = &g_G[(size_t)blk * 16384];
    #pragma unroll
    for (int mi = 0; mi < 2; mi++) {
        int r0 = wm + mi * 16 + g;
        #pragma unroll
        for (int ni = 0; ni < 8; ni++) {
            int col = wn + ni * 8 + 2 * t4;
            #pragma unroll
            for (int half = 0; half < 2; half++) {
                int r = r0 + half * 8;
                float2 v; v.x = c[mi][ni][half * 2]; v.y = c[mi][ni][half * 2 + 1];
                *(float2*)&Gout[r * 128 + col] = v;
            }
        }
    }
}

// ---------------- shared MMA pass (2-term), k-loop bounded by kmax ----------------
#define BP 136
#define XP 72
template<int TRANSA>
__device__ __forceinline__ void ssd_pass(uint32_t aHi, uint32_t aLo, uint32_t xHi,
                                         int wm, int lane, int kmax, float cacc[8][4]) {
    int l7 = lane & 7;
    int aRow = wm + ((lane >> 3) & 1) * 8 + l7;
    int aCol = (lane >> 4) * 8;
    int tL = (lane >> 4) * 8 + l7;
    int tN = ((lane >> 3) & 1) * 8;
    int bL = ((lane >> 3) & 1) * 8 + l7;
    int bP = (lane >> 4) * 8;
    #pragma unroll
    for (int term = 0; term < 2; term++) {
        uint32_t aB = (term == 1) ? aLo : aHi;
        #pragma unroll 4
        for (int k0 = 0; k0 < kmax; k0 += 16) {
            uint32_t af[4];
            if (TRANSA) {
                LDSM_X4T(af, aB + (uint32_t)(((k0 + tL) * BP + wm + tN) * 2));
            } else {
                LDSM_X4(af, aB + (uint32_t)((aRow * BP + k0 + aCol) * 2));
            }
            #pragma unroll
            for (int q = 0; q < 4; q++) {
                uint32_t bf[4];
                LDSM_X4T(bf, xHi + (uint32_t)(((k0 + bL) * XP + q * 16 + bP) * 2));
                MMA_F16(cacc[2 * q],     af, bf[0], bf[1]);
                MMA_F16(cacc[2 * q + 1], af, bf[2], bf[3]);
            }
        }
    }
}

// ---------------- causal depthwise conv1d + silu (4 s-positions/thread) ----------------
__global__ void k_conv(const float* __restrict__ conv_w, const float* __restrict__ conv_b) {
    int idx = blockIdx.x * 256 + threadIdx.x;
    int ch = idx % CONVDIM;
    int r  = idx / CONVDIM;
    int s4 = r % (SEQ / 4);
    int b  = r / (SEQ / 4);
    int s0 = s4 * 4;
    float w0 = conv_w[ch * 4], w1 = conv_w[ch * 4 + 1], w2 = conv_w[ch * 4 + 2], w3 = conv_w[ch * 4 + 3];
    float bias = conv_b[ch];
    float in[7];
    #pragma unroll
    for (int k = 0; k < 7; k++) {
        int sp = s0 + k - 3;
        in[k] = (sp >= 0) ? g_zx[(size_t)(b * SEQ + sp) * DINPROJ + DINNER + ch] : 0.f;
    }
    #pragma unroll
    for (int s = 0; s < 4; s++) {
        float acc = bias + in[s] * w0 + in[s + 1] * w1 + in[s + 2] * w2 + in[s + 3] * w3;
        acc = acc / (1.f + expf(-acc));
        g_xbc[(size_t)(b * SEQ + s0 + s) * CONVDIM + ch] = acc;
    }
}

// ---------------- dt softplus + per-chunk cumulative log-decay ----------------
__global__ void k_dtscan(const float* __restrict__ dt_bias, const float* __restrict__ A_log) {
    __shared__ float s[128];
    int blk = blockIdx.x, l = threadIdx.x;
    int h = blk & 15, c = (blk >> 4) & 15, b = blk >> 8;
    int tok = b * SEQ + c * CHUNK + l;
    float raw = g_zx[(size_t)tok * DINPROJ + 2304 + h] + dt_bias[h];
    float dtv = (raw > 20.f) ? raw : log1pf(expf(raw));
    float A = -expf(A_log[h]);
    g_dt[blk * 128 + l] = dtv;
    s[l] = dtv * A;
    __syncthreads();
    #pragma unroll
    for (int off = 1; off < 128; off <<= 1) {
        float t = (l >= off) ? s[l - off] : 0.f;
        __syncthreads();
        s[l] += t;
        __syncthreads();
    }
    g_acs[blk * 128 + l] = s[l];
}

// ---------------- per-chunk end states via tensor cores (2-term) ----------------
__global__ void __launch_bounds__(256) k_states() {
    extern __shared__ __align__(16) char sraw[];
    __half* Ahi = (__half*)sraw;
    __half* Alo = Ahi + 128 * BP;
    __half* Xhi = Alo + 128 * BP;
    float*  ws  = (float*)(Xhi + 128 * XP);
    int tid = threadIdx.x, lane = tid & 31, wid = tid >> 5;
    int blk = blockIdx.x;
    int h = blk & 15, cc = (blk >> 4) & 15, b = blk >> 8;
    int base = b * SEQ + cc * CHUNK;

    if (tid < 128) {
        float acsL = g_acs[blk * 128 + 127];
        ws[tid] = expf(acsL - g_acs[blk * 128 + tid]) * g_dt[blk * 128 + tid];
    }
    __syncthreads();
    for (int q = tid; q < 4096; q += 256) {
        int l = q >> 5, n4 = (q & 31) * 4;
        float4 v = *(const float4*)&g_xbc[(size_t)(base + l) * CONVDIM + DINNER + n4];
        float w = ws[l];
        v.x *= w; v.y *= w; v.z *= w; v.w *= w;
        split4(v, Ahi, Alo, l * BP + n4);
    }
    for (int q = tid; q < 2048; q += 256) {
        int l = q >> 4, p4 = (q & 15) * 4;
        float4 v = *(const float4*)&g_xbc[(size_t)(base + l) * CONVDIM + h * 64 + p4];
        hi4(v, Xhi, l * XP + p4);
    }
    __syncthreads();

    uint32_t bAhi = (uint32_t)__cvta_generic_to_shared(Ahi);
    uint32_t bAlo = (uint32_t)__cvta_generic_to_shared(Alo);
    uint32_t bXhi = (uint32_t)__cvta_generic_to_shared(Xhi);
    int wm = wid * 16;
    float cacc[8][4];
    #pragma unroll
    for (int ni = 0; ni < 8; ni++)
        #pragma unroll
        for (int q = 0; q < 4; q++) cacc[ni][q] = 0.f;

    ssd_pass<1>(bAhi, bAlo, bXhi, wm, lane, 128, cacc);

    int g = lane >> 2, t4 = lane & 3;
    float* d0 = &g_states[(size_t)blk * 8192 + (wm + g) * 64];
    float* d1 = d0 + 8 * 64;
    #pragma unroll
    for (int ni = 0; ni < 8; ni++) {
        int col = ni * 8 + 2 * t4;
        float2 v0; v0.x = cacc[ni][0]; v0.y = cacc[ni][1];
        float2 v1; v1.x = cacc[ni][2]; v1.y = cacc[ni][3];
        *(float2*)&d0[col] = v0;
        *(float2*)&d1[col] = v1;
    }
}

// ---------------- sequential chunk scan ----------------
__global__ void k_scan() {
    int bx = blockIdx.x;
    int e8 = bx & 7;
    int bh = bx >> 3;
    int b = bh >> 4, h = bh & 15;
    int e = e8 * 1024 + threadIdx.x;
    for (int k = 0; k < 4; k++, e += 256) {
        float acc = 0.f;
        #pragma unroll
        for (int c = 0; c < NCHUNK; c++) {
            int blk = ((b * NCHUNK + c) << 4) + h;
            g_prev[(size_t)blk * 8192 + e] = acc;
            float cd = expf(g_acs[blk * 128 + 127]);
            acc = cd * acc + g_states[(size_t)blk * 8192 + e];
        }
    }
}

// ---------------- fused SSD output; SMSP-balanced causal pass 1 ----------------
__global__ void __launch_bounds__(256) k_y(const float* __restrict__ D_head) {
    extern __shared__ __align__(16) char sraw[];
    __half* Ahi = (__half*)sraw;
    __half* Alo = Ahi + 128 * BP;
    __half* Xhi = Alo + 128 * BP;
    float* acs_s = (float*)(Xhi + 128 * XP);
    float* dt_s  = acs_s + 128;
    int tid = threadIdx.x, lane = tid & 31, wid = tid >> 5;
    int blk = blockIdx.x;
    int h = blk & 15, cc = (blk >> 4) & 15, b = blk >> 8;
    int base = b * SEQ + cc * CHUNK;
    size_t gbase = (size_t)(blk >> 4) * 16384;

    if (tid < 128) {
        acs_s[tid] = g_acs[blk * 128 + tid];
        dt_s[tid]  = g_dt[blk * 128 + tid];
    }
    __syncthreads();

    // build M and x
    for (int q = tid; q < 4096; q += 256) {
        int i = q >> 5, j4 = (q & 31) * 4;
        float ai = acs_s[i];
        float4 m;
        if (j4 + 3 <= i) {
            float4 gv = *(const float4*)&g_G[gbase + i * 128 + j4];
            m.x = expf(ai - acs_s[j4])     * dt_s[j4]     * gv.x;
            m.y = expf(ai - acs_s[j4 + 1]) * dt_s[j4 + 1] * gv.y;
            m.z = expf(ai - acs_s[j4 + 2]) * dt_s[j4 + 2] * gv.z;
            m.w = expf(ai - acs_s[j4 + 3]) * dt_s[j4 + 3] * gv.w;
        } else if (j4 <= i) {
            float4 gv = *(const float4*)&g_G[gbase + i * 128 + j4];
            m.x = (j4     <= i) ? expf(ai - acs_s[j4])     * dt_s[j4]     * gv.x : 0.f;
            m.y = (j4 + 1 <= i) ? expf(ai - acs_s[j4 + 1]) * dt_s[j4 + 1] * gv.y : 0.f;
            m.z = (j4 + 2 <= i) ? expf(ai - acs_s[j4 + 2]) * dt_s[j4 + 2] * gv.z : 0.f;
            m.w = (j4 + 3 <= i) ? expf(ai - acs_s[j4 + 3]) * dt_s[j4 + 3] * gv.w : 0.f;
        } else {
            m = make_float4(0.f, 0.f, 0.f, 0.f);
        }
        split4(m, Ahi, Alo, i * BP + j4);
    }
    for (int q = tid; q < 2048; q += 256) {
        int l = q >> 4, p4 = (q & 15) * 4;
        float4 v = *(const float4*)&g_xbc[(size_t)(base + l) * CONVDIM + h * 64 + p4];
        hi4(v, Xhi, l * XP + p4);
    }
    __syncthreads();

    uint32_t bAhi = (uint32_t)__cvta_generic_to_shared(Ahi);
    uint32_t bAlo = (uint32_t)__cvta_generic_to_shared(Alo);
    uint32_t bXhi = (uint32_t)__cvta_generic_to_shared(Xhi);
    // SMSP-balanced row-tile map: warps w and w+4 share SMSP (w&3);
    // tile = w (w<4) else 11-w gives per-SMSP pass-1 totals of 9 k-tiles each.
    int tile = (wid < 4) ? wid : (11 - wid);
    int wm = tile * 16;
    float cacc[8][4];
    #pragma unroll
    for (int ni = 0; ni < 8; ni++)
        #pragma unroll
        for (int q = 0; q < 4; q++) cacc[ni][q] = 0.f;

    // pass 1: Y_diag — rows [wm, wm+16) support j < wm+16
    ssd_pass<0>(bAhi, bAlo, bXhi, wm, lane, wm + 16, cacc);

    // D*x from resident x hi
    int g = lane >> 2, t4 = lane & 3;
    {
        float dh = D_head[h];
        int i0 = wm + g, i1 = i0 + 8;
        #pragma unroll
        for (int ni = 0; ni < 8; ni++) {
            int col = ni * 8 + 2 * t4;
            cacc[ni][0] += dh * __half2float(Xhi[i0 * XP + col]);
            cacc[ni][1] += dh * __half2float(Xhi[i0 * XP + col + 1]);
            cacc[ni][2] += dh * __half2float(Xhi[i1 * XP + col]);
            cacc[ni][3] += dh * __half2float(Xhi[i1 * XP + col + 1]);
        }
    }
    __syncthreads();

    // rebuild: A = C~, X = prev
    for (int q = tid; q < 4096; q += 256) {
        int i = q >> 5, n4 = (q & 31) * 4;
        float4 v = *(const float4*)&g_xbc[(size_t)(base + i) * CONVDIM + DINNER + DSTATE + n4];
        float e = expf(acs_s[i]);
        v.x *= e; v.y *= e; v.z *= e; v.w *= e;
        split4(v, Ahi, Alo, i * BP + n4);
    }
    for (int q = tid; q < 2048; q += 256) {
        int n = q >> 4, p4 = (q & 15) * 4;
        float4 v = *(const float4*)&g_prev[(size_t)blk * 8192 + n * 64 + p4];
        hi4(v, Xhi, n * XP + p4);
    }
    __syncthreads();

    // pass 2: Y_off (full K)
    ssd_pass<0>(bAhi, bAlo, bXhi, wm, lane, 128, cacc);

    // epilogue
    {
        int i0 = wm + g;
        float* d0 = &g_y[(size_t)(base + i0) * DINNER + h * 64];
        float* d1 = &g_y[(size_t)(base + i0 + 8) * DINNER + h * 64];
        #pragma unroll
        for (int ni = 0; ni < 8; ni++) {
            int col = ni * 8 + 2 * t4;
            float2 v0; v0.x = cacc[ni][0]; v0.y = cacc[ni][1];
            float2 v1; v1.x = cacc[ni][2]; v1.y = cacc[ni][3];
            *(float2*)&d0[col] = v0;
            *(float2*)&d1[col] = v1;
        }
    }
}

// ---------------- gate with silu(z) + RMSNorm * norm_w -> fp16 [hi|lo] ----------------
__global__ void k_gate(const float* __restrict__ norm_w, __half* __restrict__ out2) {
    __shared__ float red[64];
    int t = blockIdx.x, tid = threadIdx.x;
    float v[4]; float ss = 0.f, dummy = 0.f;
    #pragma unroll
    for (int k = 0; k < 4; k++) {
        int d = tid + k * 256;
        float yv = g_y[(size_t)t * DINNER + d];
        float zv = g_zx[(size_t)t * DINPROJ + d];
        float sv = yv * (zv / (1.f + expf(-zv)));
        v[k] = sv; ss += sv * sv;
    }
    blockReduce2(ss, dummy, red);
    float sc = rsqrtf(ss * (1.f / 1024.f) + EPSF);
    __half* row = out2 + (size_t)t * 2 * DINNER;
    #pragma unroll
    for (int k = 0; k < 4; k++) {
        int d = tid + k * 256;
        f16x2_store_scalar(row, DINNER, d, v[k] * sc * norm_w[d]);
    }
}

// ---------------- out = LayerNorm(a + b) * w + beta, optional fp16 [hi|lo] copy ----------------
__global__ void k_addln(const float* __restrict__ a, const float* __restrict__ bsrc,
                        const float* __restrict__ w, const float* __restrict__ beta,
                        float* __restrict__ o, __half* __restrict__ out2) {
    __shared__ float red[64];
    int t = blockIdx.x, tid = threadIdx.x;
    float v[4]; float s = 0.f, ssq = 0.f;
    #pragma unroll
    for (int k = 0; k < 4; k++) {
        int d = tid + k * 128;
        float x = a[(size_t)t * DMODEL + d] + bsrc[(size_t)t * DMODEL + d];
        v[k] = x; s += x; ssq += x * x;
    }
    blockReduce2(s, ssq, red);
    float mean = s * (1.f / 512.f);
    float var = ssq * (1.f / 512.f) - mean * mean;
    float inv = rsqrtf(var + EPSF);
    #pragma unroll
    for (int k = 0; k < 4; k++) {
        int d = tid + k * 128;
        float r = (v[k] - mean) * inv * w[d] + beta[d];
        o[(size_t)t * DMODEL + d] = r;
        if (out2) f16x2_store_scalar(out2 + (size_t)t * 2 * DMODEL, DMODEL, d, r);
    }
}

// ---------------- launch ----------------
extern "C" void kernel_launch(void* const* d_in, const int* in_sizes, int n_in,
                              void* d_out, int out_size) {
    const float* tgt        = (const float*)d_in[0];
    const float* in_proj_w  = (const float*)d_in[5];
    const float* conv_w     = (const float*)d_in[6];
    const float* conv_b     = (const float*)d_in[7];
    const float* dt_bias    = (const float*)d_in[8];
    const float* A_log      = (const float*)d_in[9];
    const float* D_head     = (const float*)d_in[10];
    const float* norm_w     = (const float*)d_in[11];
    const float* out_proj_w = (const float*)d_in[12];
    const float* n1w = (const float*)d_in[13];
    const float* n1b = (const float*)d_in[14];
    const float* w1  = (const float*)d_in[15];
    const float* b1  = (const float*)d_in[16];
    const float* w2  = (const float*)d_in[17];
    const float* b2  = (const float*)d_in[18];
    const float* n3w = (const float*)d_in[19];
    const float* n3b = (const float*)d_in[20];
    float* out = (float*)d_out;

    float *zx, *mo, *tb, *f2;
    __half *A2, *A2b, *W2;
    cudaGetSymbolAddress((void**)&zx,   g_zx);
    cudaGetSymbolAddress((void**)&mo,   g_mo);
    cudaGetSymbolAddress((void**)&tb,   g_t);
    cudaGetSymbolAddress((void**)&f2,   g_f2);
    cudaGetSymbolAddress((void**)&A2,   g_A2);
    cudaGetSymbolAddress((void**)&A2b,  g_A2b);
    cudaGetSymbolAddress((void**)&W2,   g_W2);

    const int smem_st = (2 * 128 * BP + 128 * XP) * 2 + 512;
    const int smem_y  = (2 * 128 * BP + 128 * XP) * 2 + 1024;
    const int smem_g  = 4 * 128 * GP * 2;
    cudaFuncSetAttribute(k_states, cudaFuncAttributeMaxDynamicSharedMemorySize, smem_st);
    cudaFuncSetAttribute(k_y,      cudaFuncAttributeMaxDynamicSharedMemorySize, smem_y);
    cudaFuncSetAttribute(k_G,      cudaFuncAttributeMaxDynamicSharedMemorySize, smem_g);

    // 1. in_proj: zx = tgt @ in_proj_w^T
    k_splitA<<<(int)(((size_t)TOK * DMODEL / 4) / 256), 256>>>(tgt, A2, DMODEL);
    k_splitW<<<(DINPROJ * DMODEL / 4) / 256, 256>>>(in_proj_w, W2);
    k_gemm_f16<0, 0><<<dim3((DINPROJ + 127) / 128, TOK / 128), 256>>>(A2, W2, nullptr, zx, DINPROJ, DMODEL);
    // 2. conv + silu
    k_conv<<<(TOK / 4 * CONVDIM) / 256, 256>>>(conv_w, conv_b);
    // 3. dt softplus + cumsum
    k_dtscan<<<NBLK, 128>>>(dt_bias, A_log);
    // 4. shared score matrices G = C @ B^T
    k_G<<<NGC, 256, smem_g>>>();
    // 5. chunk end-states (tensor core)
    k_states<<<NBLK, 256, smem_st>>>();
    // 6. chunk scan -> prev
    k_scan<<<BATCH * NHEADS * 8, 256>>>();
    // 7. fused SSD output (tensor core, balanced causal)
    k_y<<<NBLK, 256, smem_y>>>(D_head);
    // 8. gate + rmsnorm -> fp16 [hi|lo]
    k_gate<<<TOK, 256>>>(norm_w, A2);
    // 9. out_proj
    k_splitW<<<(DMODEL * DINNER / 4) / 256, 256>>>(out_proj_w, W2);
    k_gemm_f16<0, 0><<<dim3(DMODEL / 128, TOK / 128), 256>>>(A2, W2, nullptr, mo, DMODEL, DINNER);
    // 10. t = LN(tgt + mo), emit fp16 [hi|lo]
    k_addln<<<TOK, 128>>>(tgt, mo, n1w, n1b, tb, A2);
    // 11. f1 = gelu(t @ w1^T + b1) -> fp16 [hi|lo]
    k_splitW<<<(FF * DMODEL / 4) / 256, 256>>>(w1, W2);
    k_gemm_f16<1, 1><<<dim3(FF / 128, TOK / 128), 256>>>(A2, W2, b1, A2b, FF, DMODEL);
    // 12. f2 = f1 @ w2^T + b2
    k_splitW<<<(DMODEL * FF / 4) / 256, 256>>>(w2, W2);
    k_gemm_f16<0, 0><<<dim3(DMODEL / 128, TOK / 128), 256>>>(A2b, W2, b2, f2, DMODEL, FF);
    // 13. out = LN(t + f2)
    k_addln<<<TOK, 128>>>(tb, f2, n3w, n3b, out, nullptr);
}